// round 2
// baseline (speedup 1.0000x reference)
#include <cuda_runtime.h>
#include <math.h>

#define BATCH 2
#define SEQ   2048
#define DIM   1024
#define NH    16
#define HD    64
#define MTOT  (BATCH*SEQ)   // 4096

// Scratch (allocation-free rule: __device__ globals)
__device__ float g_q[MTOT*DIM];
__device__ float g_k[MTOT*DIM];
__device__ float g_v[MTOT*DIM];
__device__ float g_a[MTOT*DIM];

// ---------------------------------------------------------------------------
// SGEMM: C[M,N] = A[M,K] @ B[K,N] (+ bias over N if bias != nullptr)
// 128x128 block tile, BK=8, 256 threads, 8x8 per-thread microtile.
// (Measured at ~54% counter = near the 3-reg FFMA issue ceiling; unchanged.)
// ---------------------------------------------------------------------------
__global__ __launch_bounds__(256) void sgemm_kernel(
    const float* __restrict__ A, const float* __restrict__ B,
    float* __restrict__ C, const float* __restrict__ bias,
    int M, int N, int K)
{
    __shared__ float As[8][128];
    __shared__ float Bs[8][128];

    const int tid = threadIdx.x;
    const int bx  = blockIdx.x;   // N tile
    const int by  = blockIdx.y;   // M tile

    const int aRow = tid >> 1;          // 0..127
    const int aCol = (tid & 1) * 4;     // 0 or 4
    const int bRow = tid >> 5;          // 0..7
    const int bCol = (tid & 31) * 4;    // 0..124

    const int ty = tid >> 4;            // 0..15
    const int tx = tid & 15;            // 0..15

    const float* Aptr = A + (by * 128 + aRow) * K + aCol;
    const float* Bptr = B + bRow * N + bx * 128 + bCol;

    float acc[8][8];
    #pragma unroll
    for (int i = 0; i < 8; i++)
        #pragma unroll
        for (int j = 0; j < 8; j++)
            acc[i][j] = 0.0f;

    for (int k0 = 0; k0 < K; k0 += 8) {
        float4 a = *reinterpret_cast<const float4*>(Aptr + k0);
        float4 b = *reinterpret_cast<const float4*>(Bptr + k0 * N);

        As[aCol + 0][aRow] = a.x;
        As[aCol + 1][aRow] = a.y;
        As[aCol + 2][aRow] = a.z;
        As[aCol + 3][aRow] = a.w;
        *reinterpret_cast<float4*>(&Bs[bRow][bCol]) = b;
        __syncthreads();

        #pragma unroll
        for (int kk = 0; kk < 8; kk++) {
            float4 ra0 = *reinterpret_cast<const float4*>(&As[kk][ty * 8]);
            float4 ra1 = *reinterpret_cast<const float4*>(&As[kk][ty * 8 + 4]);
            float4 rb0 = *reinterpret_cast<const float4*>(&Bs[kk][tx * 8]);
            float4 rb1 = *reinterpret_cast<const float4*>(&Bs[kk][tx * 8 + 4]);
            float ra[8] = {ra0.x, ra0.y, ra0.z, ra0.w, ra1.x, ra1.y, ra1.z, ra1.w};
            float rb[8] = {rb0.x, rb0.y, rb0.z, rb0.w, rb1.x, rb1.y, rb1.z, rb1.w};
            #pragma unroll
            for (int i = 0; i < 8; i++)
                #pragma unroll
                for (int j = 0; j < 8; j++)
                    acc[i][j] += ra[i] * rb[j];
        }
        __syncthreads();
    }

    const int row0 = by * 128 + ty * 8;
    const int col0 = bx * 128 + tx * 8;
    const bool has_bias = (bias != nullptr);
    #pragma unroll
    for (int i = 0; i < 8; i++) {
        float4 o0, o1;
        float bv[8];
        #pragma unroll
        for (int j = 0; j < 8; j++)
            bv[j] = acc[i][j] + (has_bias ? bias[col0 + j] : 0.0f);
        o0.x = bv[0]; o0.y = bv[1]; o0.z = bv[2]; o0.w = bv[3];
        o1.x = bv[4]; o1.y = bv[5]; o1.z = bv[6]; o1.w = bv[7];
        *reinterpret_cast<float4*>(&C[(row0 + i) * N + col0])     = o0;
        *reinterpret_cast<float4*>(&C[(row0 + i) * N + col0 + 4]) = o1;
    }
}

// ---------------------------------------------------------------------------
// Flash attention (fp32, causal), v2: 4 threads per q-row.
// 256 threads = 64 q rows per block. Each thread owns 16 of the 64 head dims,
// as 4 interleaved float4 chunks: chunk indices {sub, sub+4, sub+8, sub+12}.
// With this interleave, the 4 sub-lanes of a row read ONE contiguous 64-byte
// smem segment per k -> conflict-free LDS.128, broadcast across rows.
// Score dot products are recombined with a 2-step shfl_xor butterfly (lanes
// row*4+sub, masks 1 and 2 stay inside the row's lane quad) -> all 4 lanes
// hold identical s/m/l, so softmax state stays consistent without smem.
// Regs ~70/thread -> 3 blocks/SM (24 warps, 37.5% occ) vs 8 warps before.
// ---------------------------------------------------------------------------
__global__ __launch_bounds__(256, 3) void attn_kernel(
    const float* __restrict__ Q, const float* __restrict__ K,
    const float* __restrict__ V, float* __restrict__ O)
{
    __shared__ float Ks[64][64];
    __shared__ float Vs[64][64];

    const int b   = blockIdx.z;
    const int h   = blockIdx.y;
    const int q0  = blockIdx.x * 64;
    const int tid = threadIdx.x;
    const int row = tid >> 2;     // 0..63  (q row within block)
    const int sub = tid & 3;      // 0..3   (dim-split lane)
    const int qi  = q0 + row;

    // Load this thread's 16 q dims (interleaved chunks), pre-scaled.
    const float* Qb = Q + ((long)b * SEQ + qi) * DIM + h * HD;
    float4 qv[4];
    #pragma unroll
    for (int k = 0; k < 4; k++) {
        float4 t = *reinterpret_cast<const float4*>(Qb + 4 * (sub + 4 * k));
        t.x *= 0.125f; t.y *= 0.125f; t.z *= 0.125f; t.w *= 0.125f;   // 1/sqrt(64)
        qv[k] = t;
    }

    float m = -1e30f;
    float l = 0.0f;
    float4 accv[4];
    #pragma unroll
    for (int k = 0; k < 4; k++) accv[k] = make_float4(0.f, 0.f, 0.f, 0.f);

    const float* Kbase = K + (long)b * SEQ * DIM + h * HD;
    const float* Vbase = V + (long)b * SEQ * DIM + h * HD;

    const int kv_end = q0 + 64;   // causal: last tile is the diagonal one
    for (int kv0 = 0; kv0 < kv_end; kv0 += 64) {
        __syncthreads();
        // Coalesced float4 tile loads: 1024 float4 per array, 4 per thread.
        #pragma unroll
        for (int it = 0; it < 4; it++) {
            int idx = tid + it * 256;       // 0..1023
            int r = idx >> 4, c = idx & 15;
            *reinterpret_cast<float4*>(&Ks[r][c * 4]) =
                *reinterpret_cast<const float4*>(Kbase + (long)(kv0 + r) * DIM + c * 4);
            *reinterpret_cast<float4*>(&Vs[r][c * 4]) =
                *reinterpret_cast<const float4*>(Vbase + (long)(kv0 + r) * DIM + c * 4);
        }
        __syncthreads();

        #pragma unroll 1
        for (int c8 = 0; c8 < 8; c8++) {
            float s[8];
            float cmax = -1e30f;
            #pragma unroll
            for (int jj = 0; jj < 8; jj++) {
                const int j = c8 * 8 + jj;
                float p0 = 0.0f, p1 = 0.0f;
                #pragma unroll
                for (int k = 0; k < 4; k++) {
                    float4 kk = *reinterpret_cast<const float4*>(&Ks[j][4 * (sub + 4 * k)]);
                    if (k & 1) {
                        p1 += qv[k].x * kk.x; p1 += qv[k].y * kk.y;
                        p1 += qv[k].z * kk.z; p1 += qv[k].w * kk.w;
                    } else {
                        p0 += qv[k].x * kk.x; p0 += qv[k].y * kk.y;
                        p0 += qv[k].z * kk.z; p0 += qv[k].w * kk.w;
                    }
                }
                float sv = p0 + p1;
                sv += __shfl_xor_sync(0xffffffffu, sv, 1);
                sv += __shfl_xor_sync(0xffffffffu, sv, 2);
                if (kv0 + j > qi) sv = -1e30f;   // causal mask
                s[jj] = sv;
                cmax = fmaxf(cmax, sv);
            }
            if (cmax > m) {
                float scale = __expf(m - cmax);
                m = cmax;
                l *= scale;
                #pragma unroll
                for (int k = 0; k < 4; k++) {
                    accv[k].x *= scale; accv[k].y *= scale;
                    accv[k].z *= scale; accv[k].w *= scale;
                }
            }
            #pragma unroll
            for (int jj = 0; jj < 8; jj++) {
                const int j = c8 * 8 + jj;
                float p = __expf(s[jj] - m);
                l += p;
                #pragma unroll
                for (int k = 0; k < 4; k++) {
                    float4 vv = *reinterpret_cast<const float4*>(&Vs[j][4 * (sub + 4 * k)]);
                    accv[k].x += p * vv.x; accv[k].y += p * vv.y;
                    accv[k].z += p * vv.z; accv[k].w += p * vv.w;
                }
            }
        }
    }

    const float inv_l = 1.0f / l;
    float* Ob = O + ((long)b * SEQ + qi) * DIM + h * HD;
    #pragma unroll
    for (int k = 0; k < 4; k++) {
        float4 o = accv[k];
        o.x *= inv_l; o.y *= inv_l; o.z *= inv_l; o.w *= inv_l;
        *reinterpret_cast<float4*>(Ob + 4 * (sub + 4 * k)) = o;
    }
}

// ---------------------------------------------------------------------------
// Launch
// ---------------------------------------------------------------------------
extern "C" void kernel_launch(void* const* d_in, const int* in_sizes, int n_in,
                              void* d_out, int out_size)
{
    const float* x  = (const float*)d_in[0];
    const float* Wq = (const float*)d_in[1];
    const float* Wk = (const float*)d_in[2];
    const float* Wv = (const float*)d_in[3];
    const float* Wo = (const float*)d_in[4];
    const float* bo = (const float*)d_in[5];
    float* out = (float*)d_out;

    float *qp, *kp, *vp, *ap;
    cudaGetSymbolAddress((void**)&qp, g_q);
    cudaGetSymbolAddress((void**)&kp, g_k);
    cudaGetSymbolAddress((void**)&vp, g_v);
    cudaGetSymbolAddress((void**)&ap, g_a);

    const int M = MTOT, N = DIM, K = DIM;
    dim3 gemm_grid(N / 128, M / 128);   // (8, 32)

    sgemm_kernel<<<gemm_grid, 256>>>(x, Wq, qp, nullptr, M, N, K);
    sgemm_kernel<<<gemm_grid, 256>>>(x, Wk, kp, nullptr, M, N, K);
    sgemm_kernel<<<gemm_grid, 256>>>(x, Wv, vp, nullptr, M, N, K);

    dim3 attn_grid(SEQ / 64, NH, BATCH);   // (32, 16, 2)
    attn_kernel<<<attn_grid, 256>>>(qp, kp, vp, ap);

    sgemm_kernel<<<gemm_grid, 256>>>(ap, Wo, out, bo, M, N, K);
}

// round 4
// speedup vs baseline: 1.8022x; 1.8022x over previous
#include <cuda_runtime.h>
#include <math.h>
#include <stdint.h>

#define BATCH 2
#define SEQ   2048
#define DIM   1024
#define NH    16
#define HD    64
#define MTOT  (BATCH*SEQ)   // 4096

// ---------------------------------------------------------------------------
// Scratch (allocation-free rule: __device__ globals)
// ---------------------------------------------------------------------------
__device__ float g_q[MTOT*DIM];
__device__ float g_k[MTOT*DIM];
__device__ float g_v[MTOT*DIM];
__device__ float g_a[MTOT*DIM];
// Transposed weights, stored as tf32 bit patterns: WT[n][k] = tf32(W[k][n])
__device__ float g_wqt[DIM*DIM];
__device__ float g_wkt[DIM*DIM];
__device__ float g_wvt[DIM*DIM];
__device__ float g_wot[DIM*DIM];

// ---------------------------------------------------------------------------
// Helpers
// ---------------------------------------------------------------------------
__device__ __forceinline__ uint32_t f2tf32(float f) {
    uint32_t u;
    asm("cvt.rna.tf32.f32 %0, %1;" : "=r"(u) : "f"(f));
    return u;
}

#define MMA_TF32(d, a, b) \
    asm volatile("mma.sync.aligned.m16n8k8.row.col.f32.tf32.tf32.f32 " \
        "{%0,%1,%2,%3}, {%4,%5,%6,%7}, {%8,%9}, {%0,%1,%2,%3};" \
        : "+f"((d)[0]), "+f"((d)[1]), "+f"((d)[2]), "+f"((d)[3]) \
        : "r"((a)[0]), "r"((a)[1]), "r"((a)[2]), "r"((a)[3]), \
          "r"((b)[0]), "r"((b)[1]))

// ---------------------------------------------------------------------------
// Transpose + tf32-convert: W[K,N] fp32 -> WT[N,K] (tf32 bit patterns)
// ---------------------------------------------------------------------------
__global__ __launch_bounds__(256) void transpose_tf32_kernel(
    const float* __restrict__ W, float* __restrict__ WT)
{
    __shared__ float tile[32][33];
    const int k0 = blockIdx.y * 32;
    const int n0 = blockIdx.x * 32;
    const int tx = threadIdx.x;      // 0..31
    const int ty = threadIdx.y;      // 0..7
    #pragma unroll
    for (int i = ty; i < 32; i += 8)
        tile[i][tx] = W[(size_t)(k0 + i) * DIM + n0 + tx];
    __syncthreads();
    #pragma unroll
    for (int i = ty; i < 32; i += 8) {
        uint32_t u = f2tf32(tile[tx][i]);      // = tf32(W[k0+tx][n0+i])
        reinterpret_cast<uint32_t*>(WT)[(size_t)(n0 + i) * DIM + k0 + tx] = u;
    }
}

// ---------------------------------------------------------------------------
// tf32 tensor-core GEMM: C[4096,1024] = A[4096,1024] @ B[1024,1024] (+bias)
//   A fp32 (tf32-converted on the fly), BT pre-transposed tf32 [N,K].
// CTA tile 128x128, BK=32 double-buffered, 8 warps, warp tile 64x32,
// mma.sync.m16n8k8. Smem rows padded to 36 floats -> fragment loads hit
// banks (4*row+col) mod 32: all 32 lanes distinct -> conflict-free.
// Register prefetch pipeline, ONE __syncthreads per K stage.
// ---------------------------------------------------------------------------
#define ASTRIDE      36
#define STAGE_FLOATS (128*ASTRIDE)        // 4608 floats per tile
#define BUF_FLOATS   (2*STAGE_FLOATS)     // A+B per stage
#define GEMM_SMEM    (2*BUF_FLOATS*4)     // 73728 B

__global__ __launch_bounds__(256) void gemm_tf32_kernel(
    const float* __restrict__ A, const float* __restrict__ BT,
    float* __restrict__ C, const float* __restrict__ bias)
{
    extern __shared__ float sm[];
    const int tid  = threadIdx.x;
    const int lane = tid & 31;
    const int wid  = tid >> 5;
    const int wm   = wid & 1;        // 2 warps in M
    const int wn   = wid >> 1;       // 4 warps in N
    const int bx   = blockIdx.x;     // N tile
    const int by   = blockIdx.y;     // M tile

    const int lr = tid >> 3;         // 0..31 (row group for gmem loads)
    const int lq = tid & 7;          // 0..7  (16B segment within 128B row)

    const float* Ag = A  + (size_t)(by * 128 + lr) * DIM + lq * 4;
    const float* Bg = BT + (size_t)(bx * 128 + lr) * DIM + lq * 4;

    float c[4][4][4];
    #pragma unroll
    for (int i = 0; i < 4; i++)
        #pragma unroll
        for (int j = 0; j < 4; j++)
            #pragma unroll
            for (int k = 0; k < 4; k++)
                c[i][j][k] = 0.0f;

    float4 pa[4], pb[4];
    #pragma unroll
    for (int j = 0; j < 4; j++) {
        pa[j] = *reinterpret_cast<const float4*>(Ag + (size_t)j * 32 * DIM);
        pb[j] = *reinterpret_cast<const float4*>(Bg + (size_t)j * 32 * DIM);
    }

    auto store_stage = [&](int b) {
        float* As = sm + b * BUF_FLOATS;
        float* Bs = As + STAGE_FLOATS;
        #pragma unroll
        for (int j = 0; j < 4; j++) {
            uint32_t* uA = reinterpret_cast<uint32_t*>(As + (lr + 32 * j) * ASTRIDE + lq * 4);
            uA[0] = f2tf32(pa[j].x); uA[1] = f2tf32(pa[j].y);
            uA[2] = f2tf32(pa[j].z); uA[3] = f2tf32(pa[j].w);
            // BT is already tf32 bit patterns
            *reinterpret_cast<float4*>(Bs + (lr + 32 * j) * ASTRIDE + lq * 4) = pb[j];
        }
    };
    store_stage(0);
    __syncthreads();

    const int NS = DIM / 32;   // 32 stages
    for (int s = 0; s < NS; s++) {
        const int cur = s & 1;
        if (s + 1 < NS) {
            const float* Ags = Ag + (s + 1) * 32;
            const float* Bgs = Bg + (s + 1) * 32;
            #pragma unroll
            for (int j = 0; j < 4; j++) {
                pa[j] = *reinterpret_cast<const float4*>(Ags + (size_t)j * 32 * DIM);
                pb[j] = *reinterpret_cast<const float4*>(Bgs + (size_t)j * 32 * DIM);
            }
        }
        const uint32_t* Au = reinterpret_cast<const uint32_t*>(sm + cur * BUF_FLOATS);
        const uint32_t* Bu = Au + STAGE_FLOATS;

        #pragma unroll
        for (int kk = 0; kk < 4; kk++) {
            uint32_t af[4][4], bf[4][2];
            const int col = kk * 8 + (lane & 3);
            const int r0  = wm * 64 + (lane >> 2);
            #pragma unroll
            for (int am = 0; am < 4; am++) {
                const uint32_t* p = Au + (r0 + am * 16) * ASTRIDE + col;
                af[am][0] = p[0];
                af[am][1] = p[8 * ASTRIDE];
                af[am][2] = p[4];
                af[am][3] = p[8 * ASTRIDE + 4];
            }
            #pragma unroll
            for (int bn = 0; bn < 4; bn++) {
                const uint32_t* p = Bu + (wn * 32 + bn * 8 + (lane >> 2)) * ASTRIDE + col;
                bf[bn][0] = p[0];
                bf[bn][1] = p[4];
            }
            #pragma unroll
            for (int am = 0; am < 4; am++)
                #pragma unroll
                for (int bn = 0; bn < 4; bn++)
                    MMA_TF32(c[am][bn], af[am], bf[bn]);
        }

        if (s + 1 < NS) {
            store_stage(1 - cur);
            __syncthreads();
        }
    }

    // Epilogue: c frag (am,bn): rows r0, r0+8; cols 2*(lane%4), +1
    const int rbase = by * 128 + wm * 64 + (lane >> 2);
    const int cbase = bx * 128 + wn * 32 + (lane & 3) * 2;
    #pragma unroll
    for (int am = 0; am < 4; am++) {
        #pragma unroll
        for (int bn = 0; bn < 4; bn++) {
            const int col = cbase + bn * 8;
            const int r0  = rbase + am * 16;
            float b0 = bias ? bias[col]     : 0.0f;
            float b1 = bias ? bias[col + 1] : 0.0f;
            float2 v0 = make_float2(c[am][bn][0] + b0, c[am][bn][1] + b1);
            float2 v1 = make_float2(c[am][bn][2] + b0, c[am][bn][3] + b1);
            *reinterpret_cast<float2*>(C + (size_t)r0 * DIM + col)       = v0;
            *reinterpret_cast<float2*>(C + (size_t)(r0 + 8) * DIM + col) = v1;
        }
    }
}

// ---------------------------------------------------------------------------
// Flash attention (fp32, causal) — proven R1 version (955us).
// ---------------------------------------------------------------------------
__global__ __launch_bounds__(128) void attn_kernel(
    const float* __restrict__ Q, const float* __restrict__ K,
    const float* __restrict__ V, float* __restrict__ O)
{
    __shared__ float Ks[64][64];
    __shared__ float Vs[64][64];

    const int b   = blockIdx.z;
    const int h   = blockIdx.y;
    const int q0  = blockIdx.x * 128;
    const int tid = threadIdx.x;
    const int qi  = q0 + tid;

    const float* Qb = Q + ((long)b * SEQ + qi) * DIM + h * HD;
    float qreg[64];
    #pragma unroll
    for (int d = 0; d < 64; d++)
        qreg[d] = Qb[d] * 0.125f;   // 1/sqrt(64)

    float m = -1e30f;
    float l = 0.0f;
    float acc[64];
    #pragma unroll
    for (int d = 0; d < 64; d++) acc[d] = 0.0f;

    const float* Kbase = K + (long)b * SEQ * DIM + h * HD;
    const float* Vbase = V + (long)b * SEQ * DIM + h * HD;

    const int kv_end = q0 + 128;
    for (int kv0 = 0; kv0 < kv_end; kv0 += 64) {
        __syncthreads();
        #pragma unroll
        for (int it = 0; it < 32; it++) {
            int idx = tid + it * 128;
            int r = idx >> 6, cc = idx & 63;
            Ks[r][cc] = Kbase[(long)(kv0 + r) * DIM + cc];
            Vs[r][cc] = Vbase[(long)(kv0 + r) * DIM + cc];
        }
        __syncthreads();

        #pragma unroll 1
        for (int c4 = 0; c4 < 4; c4++) {
            float s[16];
            float cmax = -1e30f;
            #pragma unroll
            for (int jj = 0; jj < 16; jj++) {
                const int j = c4 * 16 + jj;
                float sv = 0.0f;
                #pragma unroll
                for (int d4 = 0; d4 < 16; d4++) {
                    float4 kk = *reinterpret_cast<const float4*>(&Ks[j][d4 * 4]);
                    sv += qreg[d4 * 4 + 0] * kk.x;
                    sv += qreg[d4 * 4 + 1] * kk.y;
                    sv += qreg[d4 * 4 + 2] * kk.z;
                    sv += qreg[d4 * 4 + 3] * kk.w;
                }
                if (kv0 + j > qi) sv = -1e30f;
                s[jj] = sv;
                cmax = fmaxf(cmax, sv);
            }
            if (cmax > m) {
                float scale = __expf(m - cmax);
                m = cmax;
                l *= scale;
                #pragma unroll
                for (int d = 0; d < 64; d++) acc[d] *= scale;
            }
            #pragma unroll
            for (int jj = 0; jj < 16; jj++) {
                const int j = c4 * 16 + jj;
                float p = __expf(s[jj] - m);
                l += p;
                #pragma unroll
                for (int d4 = 0; d4 < 16; d4++) {
                    float4 vv = *reinterpret_cast<const float4*>(&Vs[j][d4 * 4]);
                    acc[d4 * 4 + 0] += p * vv.x;
                    acc[d4 * 4 + 1] += p * vv.y;
                    acc[d4 * 4 + 2] += p * vv.z;
                    acc[d4 * 4 + 3] += p * vv.w;
                }
            }
        }
    }

    const float inv_l = 1.0f / l;
    float* Ob = O + ((long)b * SEQ + qi) * DIM + h * HD;
    #pragma unroll
    for (int d = 0; d < 64; d++)
        Ob[d] = acc[d] * inv_l;
}

// ---------------------------------------------------------------------------
// Launch
// ---------------------------------------------------------------------------
extern "C" void kernel_launch(void* const* d_in, const int* in_sizes, int n_in,
                              void* d_out, int out_size)
{
    const float* x  = (const float*)d_in[0];
    const float* Wq = (const float*)d_in[1];
    const float* Wk = (const float*)d_in[2];
    const float* Wv = (const float*)d_in[3];
    const float* Wo = (const float*)d_in[4];
    const float* bo = (const float*)d_in[5];
    float* out = (float*)d_out;

    float *qp, *kp, *vp, *ap, *wqt, *wkt, *wvt, *wot;
    cudaGetSymbolAddress((void**)&qp,  g_q);
    cudaGetSymbolAddress((void**)&kp,  g_k);
    cudaGetSymbolAddress((void**)&vp,  g_v);
    cudaGetSymbolAddress((void**)&ap,  g_a);
    cudaGetSymbolAddress((void**)&wqt, g_wqt);
    cudaGetSymbolAddress((void**)&wkt, g_wkt);
    cudaGetSymbolAddress((void**)&wvt, g_wvt);
    cudaGetSymbolAddress((void**)&wot, g_wot);

    cudaFuncSetAttribute(gemm_tf32_kernel,
                         cudaFuncAttributeMaxDynamicSharedMemorySize, GEMM_SMEM);

    dim3 wt_grid(DIM / 32, DIM / 32);
    dim3 wt_block(32, 8);
    transpose_tf32_kernel<<<wt_grid, wt_block>>>(Wq, wqt);
    transpose_tf32_kernel<<<wt_grid, wt_block>>>(Wk, wkt);
    transpose_tf32_kernel<<<wt_grid, wt_block>>>(Wv, wvt);
    transpose_tf32_kernel<<<wt_grid, wt_block>>>(Wo, wot);

    dim3 gemm_grid(DIM / 128, MTOT / 128);   // (8, 32)
    gemm_tf32_kernel<<<gemm_grid, 256, GEMM_SMEM>>>(x, wqt, qp, nullptr);
    gemm_tf32_kernel<<<gemm_grid, 256, GEMM_SMEM>>>(x, wkt, kp, nullptr);
    gemm_tf32_kernel<<<gemm_grid, 256, GEMM_SMEM>>>(x, wvt, vp, nullptr);

    dim3 attn_grid(SEQ / 128, NH, BATCH);    // (16, 16, 2)
    attn_kernel<<<attn_grid, 128>>>(qp, kp, vp, ap);

    gemm_tf32_kernel<<<gemm_grid, 256, GEMM_SMEM>>>(ap, wot, out, bo);
}

// round 5
// speedup vs baseline: 3.9831x; 2.2101x over previous
#include <cuda_runtime.h>
#include <math.h>
#include <stdint.h>

#define BATCH 2
#define SEQ   2048
#define DIM   1024
#define NH    16
#define HD    64
#define MTOT  (BATCH*SEQ)   // 4096

// ---------------------------------------------------------------------------
// Scratch (allocation-free rule: __device__ globals)
// ---------------------------------------------------------------------------
__device__ float g_q[MTOT*DIM];
__device__ float g_k[MTOT*DIM];
__device__ float g_v[MTOT*DIM];
__device__ float g_a[MTOT*DIM];
// Transposed weights, stored as tf32 bit patterns: WT[n][k] = tf32(W[k][n])
__device__ float g_wqt[DIM*DIM];
__device__ float g_wkt[DIM*DIM];
__device__ float g_wvt[DIM*DIM];
__device__ float g_wot[DIM*DIM];

// ---------------------------------------------------------------------------
// Helpers
// ---------------------------------------------------------------------------
__device__ __forceinline__ uint32_t f2tf32(float f) {
    uint32_t u;
    asm("cvt.rna.tf32.f32 %0, %1;" : "=r"(u) : "f"(f));
    return u;
}

#define MMA_TF32(d, a, b) \
    asm volatile("mma.sync.aligned.m16n8k8.row.col.f32.tf32.tf32.f32 " \
        "{%0,%1,%2,%3}, {%4,%5,%6,%7}, {%8,%9}, {%0,%1,%2,%3};" \
        : "+f"((d)[0]), "+f"((d)[1]), "+f"((d)[2]), "+f"((d)[3]) \
        : "r"((a)[0]), "r"((a)[1]), "r"((a)[2]), "r"((a)[3]), \
          "r"((b)[0]), "r"((b)[1]))

// ---------------------------------------------------------------------------
// Transpose + tf32-convert: W[K,N] fp32 -> WT[N,K] (tf32 bit patterns)
// ---------------------------------------------------------------------------
__global__ __launch_bounds__(256) void transpose_tf32_kernel(
    const float* __restrict__ W, float* __restrict__ WT)
{
    __shared__ float tile[32][33];
    const int k0 = blockIdx.y * 32;
    const int n0 = blockIdx.x * 32;
    const int tx = threadIdx.x;      // 0..31
    const int ty = threadIdx.y;      // 0..7
    #pragma unroll
    for (int i = ty; i < 32; i += 8)
        tile[i][tx] = W[(size_t)(k0 + i) * DIM + n0 + tx];
    __syncthreads();
    #pragma unroll
    for (int i = ty; i < 32; i += 8) {
        uint32_t u = f2tf32(tile[tx][i]);      // = tf32(W[k0+tx][n0+i])
        reinterpret_cast<uint32_t*>(WT)[(size_t)(n0 + i) * DIM + k0 + tx] = u;
    }
}

// ---------------------------------------------------------------------------
// tf32 tensor-core GEMM (unchanged from R4; measured good).
// ---------------------------------------------------------------------------
#define ASTRIDE      36
#define STAGE_FLOATS (128*ASTRIDE)
#define BUF_FLOATS   (2*STAGE_FLOATS)
#define GEMM_SMEM    (2*BUF_FLOATS*4)

__global__ __launch_bounds__(256) void gemm_tf32_kernel(
    const float* __restrict__ A, const float* __restrict__ BT,
    float* __restrict__ C, const float* __restrict__ bias)
{
    extern __shared__ float sm[];
    const int tid  = threadIdx.x;
    const int lane = tid & 31;
    const int wid  = tid >> 5;
    const int wm   = wid & 1;
    const int wn   = wid >> 1;
    const int bx   = blockIdx.x;
    const int by   = blockIdx.y;

    const int lr = tid >> 3;
    const int lq = tid & 7;

    const float* Ag = A  + (size_t)(by * 128 + lr) * DIM + lq * 4;
    const float* Bg = BT + (size_t)(bx * 128 + lr) * DIM + lq * 4;

    float c[4][4][4];
    #pragma unroll
    for (int i = 0; i < 4; i++)
        #pragma unroll
        for (int j = 0; j < 4; j++)
            #pragma unroll
            for (int k = 0; k < 4; k++)
                c[i][j][k] = 0.0f;

    float4 pa[4], pb[4];
    #pragma unroll
    for (int j = 0; j < 4; j++) {
        pa[j] = *reinterpret_cast<const float4*>(Ag + (size_t)j * 32 * DIM);
        pb[j] = *reinterpret_cast<const float4*>(Bg + (size_t)j * 32 * DIM);
    }

    auto store_stage = [&](int b) {
        float* As = sm + b * BUF_FLOATS;
        float* Bs = As + STAGE_FLOATS;
        #pragma unroll
        for (int j = 0; j < 4; j++) {
            uint32_t* uA = reinterpret_cast<uint32_t*>(As + (lr + 32 * j) * ASTRIDE + lq * 4);
            uA[0] = f2tf32(pa[j].x); uA[1] = f2tf32(pa[j].y);
            uA[2] = f2tf32(pa[j].z); uA[3] = f2tf32(pa[j].w);
            *reinterpret_cast<float4*>(Bs + (lr + 32 * j) * ASTRIDE + lq * 4) = pb[j];
        }
    };
    store_stage(0);
    __syncthreads();

    const int NS = DIM / 32;
    for (int s = 0; s < NS; s++) {
        const int cur = s & 1;
        if (s + 1 < NS) {
            const float* Ags = Ag + (s + 1) * 32;
            const float* Bgs = Bg + (s + 1) * 32;
            #pragma unroll
            for (int j = 0; j < 4; j++) {
                pa[j] = *reinterpret_cast<const float4*>(Ags + (size_t)j * 32 * DIM);
                pb[j] = *reinterpret_cast<const float4*>(Bgs + (size_t)j * 32 * DIM);
            }
        }
        const uint32_t* Au = reinterpret_cast<const uint32_t*>(sm + cur * BUF_FLOATS);
        const uint32_t* Bu = Au + STAGE_FLOATS;

        #pragma unroll
        for (int kk = 0; kk < 4; kk++) {
            uint32_t af[4][4], bf[4][2];
            const int col = kk * 8 + (lane & 3);
            const int r0  = wm * 64 + (lane >> 2);
            #pragma unroll
            for (int am = 0; am < 4; am++) {
                const uint32_t* p = Au + (r0 + am * 16) * ASTRIDE + col;
                af[am][0] = p[0];
                af[am][1] = p[8 * ASTRIDE];
                af[am][2] = p[4];
                af[am][3] = p[8 * ASTRIDE + 4];
            }
            #pragma unroll
            for (int bn = 0; bn < 4; bn++) {
                const uint32_t* p = Bu + (wn * 32 + bn * 8 + (lane >> 2)) * ASTRIDE + col;
                bf[bn][0] = p[0];
                bf[bn][1] = p[4];
            }
            #pragma unroll
            for (int am = 0; am < 4; am++)
                #pragma unroll
                for (int bn = 0; bn < 4; bn++)
                    MMA_TF32(c[am][bn], af[am], bf[bn]);
        }

        if (s + 1 < NS) {
            store_stage(1 - cur);
            __syncthreads();
        }
    }

    const int rbase = by * 128 + wm * 64 + (lane >> 2);
    const int cbase = bx * 128 + wn * 32 + (lane & 3) * 2;
    #pragma unroll
    for (int am = 0; am < 4; am++) {
        #pragma unroll
        for (int bn = 0; bn < 4; bn++) {
            const int col = cbase + bn * 8;
            const int r0  = rbase + am * 16;
            float b0 = bias ? bias[col]     : 0.0f;
            float b1 = bias ? bias[col + 1] : 0.0f;
            float2 v0 = make_float2(c[am][bn][0] + b0, c[am][bn][1] + b1);
            float2 v1 = make_float2(c[am][bn][2] + b0, c[am][bn][3] + b1);
            *reinterpret_cast<float2*>(C + (size_t)r0 * DIM + col)       = v0;
            *reinterpret_cast<float2*>(C + (size_t)(r0 + 8) * DIM + col) = v1;
        }
    }
}

// ---------------------------------------------------------------------------
// Tensor-core flash attention (tf32 mma.sync, causal).
// CTA: 128 threads = 4 warps, 64 q rows (16 per warp). kv tiles of 64.
// QK^T uses 3xTF32 split (qhi/qlo regs, Khi/Klo smem) -> ~fp32-accurate scores.
// PV single-pass tf32. P re-laid out via warp-private smem rows + __syncwarp.
// All smem strides 68 floats -> conflict-free fragment LDS.
// ---------------------------------------------------------------------------
#define AST 68
#define ATTN_SMEM (4*64*AST*4)   // Ps/Qs, Khi, Klo, Vs = 69632 B

__global__ __launch_bounds__(128, 2) void attn_tc_kernel(
    const float* __restrict__ Q, const float* __restrict__ K,
    const float* __restrict__ V, float* __restrict__ Oout)
{
    extern __shared__ float smem[];
    float* Ps  = smem;                // [64][AST]: Q (prologue) then P tiles
    float* Khi = smem + 64 * AST;
    float* Klo = Khi + 64 * AST;
    float* Vs  = Klo + 64 * AST;

    const int b    = blockIdx.z;
    const int h    = blockIdx.y;
    const int q0   = (gridDim.x - 1 - blockIdx.x) * 64;  // heavy blocks first
    const int tid  = threadIdx.x;
    const int wq   = tid >> 5;
    const int lane = tid & 31;
    const int gid  = lane >> 2;      // 0..7
    const int tig  = lane & 3;       // 0..3

    const float* Qg = Q + (size_t)b * SEQ * DIM + h * HD;
    const float* Kg = K + (size_t)b * SEQ * DIM + h * HD;
    const float* Vg = V + (size_t)b * SEQ * DIM + h * HD;

    // ---- Prologue: Q tile (scaled) -> smem, then per-warp hi/lo fragments
    #pragma unroll
    for (int i = 0; i < 8; i++) {
        int idx = tid + i * 128;             // 0..1023 float4 slots
        int r = idx >> 4, c = (idx & 15) * 4;
        float4 v4 = *reinterpret_cast<const float4*>(Qg + (size_t)(q0 + r) * DIM + c);
        Ps[r * AST + c + 0] = v4.x * 0.125f;
        Ps[r * AST + c + 1] = v4.y * 0.125f;
        Ps[r * AST + c + 2] = v4.z * 0.125f;
        Ps[r * AST + c + 3] = v4.w * 0.125f;
    }
    __syncthreads();

    uint32_t qhi[8][4], qlo[8][4];
    {
        const int rr = wq * 16 + gid;
        #pragma unroll
        for (int kt = 0; kt < 8; kt++) {
            const int cc = kt * 8 + tig;
            float f[4];
            f[0] = Ps[rr * AST + cc];
            f[1] = Ps[(rr + 8) * AST + cc];
            f[2] = Ps[rr * AST + cc + 4];
            f[3] = Ps[(rr + 8) * AST + cc + 4];
            #pragma unroll
            for (int e = 0; e < 4; e++) {
                qhi[kt][e] = f2tf32(f[e]);
                qlo[kt][e] = f2tf32(f[e] - __uint_as_float(qhi[kt][e]));
            }
        }
    }
    // No extra sync: each warp only reads/writes its own 16 rows of Ps below.

    float m0 = -1e30f, m1 = -1e30f, l0 = 0.0f, l1 = 0.0f;
    float o[8][4];
    #pragma unroll
    for (int nt = 0; nt < 8; nt++)
        #pragma unroll
        for (int e = 0; e < 4; e++) o[nt][e] = 0.0f;

    const int ntiles = (q0 >> 6) + 1;
    for (int t = 0; t < ntiles; t++) {
        const int kv0 = t * 64;
        __syncthreads();
        // ---- Load K (split hi/lo) and V (tf32) tiles
        #pragma unroll
        for (int i = 0; i < 8; i++) {
            int idx = tid + i * 128;
            int r = idx >> 4, c = (idx & 15) * 4;
            float4 kk = *reinterpret_cast<const float4*>(Kg + (size_t)(kv0 + r) * DIM + c);
            float kv[4] = {kk.x, kk.y, kk.z, kk.w};
            #pragma unroll
            for (int e = 0; e < 4; e++) {
                uint32_t hi = f2tf32(kv[e]);
                Khi[r * AST + c + e] = __uint_as_float(hi);
                Klo[r * AST + c + e] = __uint_as_float(f2tf32(kv[e] - __uint_as_float(hi)));
            }
            float4 vv = *reinterpret_cast<const float4*>(Vg + (size_t)(kv0 + r) * DIM + c);
            Vs[r * AST + c + 0] = __uint_as_float(f2tf32(vv.x));
            Vs[r * AST + c + 1] = __uint_as_float(f2tf32(vv.y));
            Vs[r * AST + c + 2] = __uint_as_float(f2tf32(vv.z));
            Vs[r * AST + c + 3] = __uint_as_float(f2tf32(vv.w));
        }
        __syncthreads();

        // ---- S = Q @ K^T  (3xTF32)
        float s[8][4];
        #pragma unroll
        for (int nt = 0; nt < 8; nt++)
            #pragma unroll
            for (int e = 0; e < 4; e++) s[nt][e] = 0.0f;

        #pragma unroll
        for (int kt = 0; kt < 8; kt++) {
            #pragma unroll
            for (int nt = 0; nt < 8; nt++) {
                const int boff = (nt * 8 + gid) * AST + kt * 8 + tig;
                uint32_t bh[2], bl[2];
                bh[0] = __float_as_uint(Khi[boff]);
                bh[1] = __float_as_uint(Khi[boff + 4]);
                bl[0] = __float_as_uint(Klo[boff]);
                bl[1] = __float_as_uint(Klo[boff + 4]);
                MMA_TF32(s[nt], qhi[kt], bh);
                MMA_TF32(s[nt], qlo[kt], bh);
                MMA_TF32(s[nt], qhi[kt], bl);
            }
        }

        // ---- Causal mask (only the diagonal tile needs it)
        const int r0g = q0 + wq * 16 + gid;
        const int r1g = r0g + 8;
        if (kv0 == q0) {
            #pragma unroll
            for (int nt = 0; nt < 8; nt++) {
                const int c0 = kv0 + nt * 8 + 2 * tig;
                if (c0     > r0g) s[nt][0] = -1e30f;
                if (c0 + 1 > r0g) s[nt][1] = -1e30f;
                if (c0     > r1g) s[nt][2] = -1e30f;
                if (c0 + 1 > r1g) s[nt][3] = -1e30f;
            }
        }

        // ---- Online softmax (rows r0g, r1g per lane quad)
        float mx0 = -1e30f, mx1 = -1e30f;
        #pragma unroll
        for (int nt = 0; nt < 8; nt++) {
            mx0 = fmaxf(mx0, fmaxf(s[nt][0], s[nt][1]));
            mx1 = fmaxf(mx1, fmaxf(s[nt][2], s[nt][3]));
        }
        mx0 = fmaxf(mx0, __shfl_xor_sync(0xffffffffu, mx0, 1));
        mx0 = fmaxf(mx0, __shfl_xor_sync(0xffffffffu, mx0, 2));
        mx1 = fmaxf(mx1, __shfl_xor_sync(0xffffffffu, mx1, 1));
        mx1 = fmaxf(mx1, __shfl_xor_sync(0xffffffffu, mx1, 2));

        const float nm0 = fmaxf(m0, mx0);
        const float nm1 = fmaxf(m1, mx1);
        const float sc0 = __expf(m0 - nm0);
        const float sc1 = __expf(m1 - nm1);
        m0 = nm0; m1 = nm1;
        l0 *= sc0; l1 *= sc1;

        float sum0 = 0.0f, sum1 = 0.0f;
        float* pp = Ps + (wq * 16 + gid) * AST + 2 * tig;
        #pragma unroll
        for (int nt = 0; nt < 8; nt++) {
            float p00 = __expf(s[nt][0] - m0);
            float p01 = __expf(s[nt][1] - m0);
            float p10 = __expf(s[nt][2] - m1);
            float p11 = __expf(s[nt][3] - m1);
            sum0 += p00 + p01;
            sum1 += p10 + p11;
            pp[nt * 8]               = __uint_as_float(f2tf32(p00));
            pp[nt * 8 + 1]           = __uint_as_float(f2tf32(p01));
            pp[8 * AST + nt * 8]     = __uint_as_float(f2tf32(p10));
            pp[8 * AST + nt * 8 + 1] = __uint_as_float(f2tf32(p11));
            o[nt][0] *= sc0; o[nt][1] *= sc0;
            o[nt][2] *= sc1; o[nt][3] *= sc1;
        }
        sum0 += __shfl_xor_sync(0xffffffffu, sum0, 1);
        sum0 += __shfl_xor_sync(0xffffffffu, sum0, 2);
        sum1 += __shfl_xor_sync(0xffffffffu, sum1, 1);
        sum1 += __shfl_xor_sync(0xffffffffu, sum1, 2);
        l0 += sum0; l1 += sum1;

        __syncwarp();

        // ---- O += P @ V
        #pragma unroll
        for (int kt = 0; kt < 8; kt++) {
            uint32_t a[4];
            const float* ap = Ps + (wq * 16 + gid) * AST + kt * 8 + tig;
            a[0] = __float_as_uint(ap[0]);
            a[1] = __float_as_uint(ap[8 * AST]);
            a[2] = __float_as_uint(ap[4]);
            a[3] = __float_as_uint(ap[8 * AST + 4]);
            #pragma unroll
            for (int nt = 0; nt < 8; nt++) {
                const float* bp = Vs + (kt * 8 + tig) * AST + nt * 8 + gid;
                uint32_t bb[2];
                bb[0] = __float_as_uint(bp[0]);
                bb[1] = __float_as_uint(bp[4 * AST]);
                MMA_TF32(o[nt], a, bb);
            }
        }
        __syncwarp();   // Ps rewritten next tile only after all lanes done reading
    }

    // ---- Epilogue
    const float inv0 = 1.0f / l0;
    const float inv1 = 1.0f / l1;
    const int r0g = q0 + wq * 16 + gid;
    float* Og = Oout + (size_t)b * SEQ * DIM + h * HD;
    #pragma unroll
    for (int nt = 0; nt < 8; nt++) {
        const int col = nt * 8 + 2 * tig;
        float2 v0 = make_float2(o[nt][0] * inv0, o[nt][1] * inv0);
        float2 v1 = make_float2(o[nt][2] * inv1, o[nt][3] * inv1);
        *reinterpret_cast<float2*>(Og + (size_t)r0g * DIM + col)       = v0;
        *reinterpret_cast<float2*>(Og + (size_t)(r0g + 8) * DIM + col) = v1;
    }
}

// ---------------------------------------------------------------------------
// Launch
// ---------------------------------------------------------------------------
extern "C" void kernel_launch(void* const* d_in, const int* in_sizes, int n_in,
                              void* d_out, int out_size)
{
    const float* x  = (const float*)d_in[0];
    const float* Wq = (const float*)d_in[1];
    const float* Wk = (const float*)d_in[2];
    const float* Wv = (const float*)d_in[3];
    const float* Wo = (const float*)d_in[4];
    const float* bo = (const float*)d_in[5];
    float* out = (float*)d_out;

    float *qp, *kp, *vp, *ap, *wqt, *wkt, *wvt, *wot;
    cudaGetSymbolAddress((void**)&qp,  g_q);
    cudaGetSymbolAddress((void**)&kp,  g_k);
    cudaGetSymbolAddress((void**)&vp,  g_v);
    cudaGetSymbolAddress((void**)&ap,  g_a);
    cudaGetSymbolAddress((void**)&wqt, g_wqt);
    cudaGetSymbolAddress((void**)&wkt, g_wkt);
    cudaGetSymbolAddress((void**)&wvt, g_wvt);
    cudaGetSymbolAddress((void**)&wot, g_wot);

    cudaFuncSetAttribute(gemm_tf32_kernel,
                         cudaFuncAttributeMaxDynamicSharedMemorySize, GEMM_SMEM);
    cudaFuncSetAttribute(attn_tc_kernel,
                         cudaFuncAttributeMaxDynamicSharedMemorySize, ATTN_SMEM);

    dim3 wt_grid(DIM / 32, DIM / 32);
    dim3 wt_block(32, 8);
    transpose_tf32_kernel<<<wt_grid, wt_block>>>(Wq, wqt);
    transpose_tf32_kernel<<<wt_grid, wt_block>>>(Wk, wkt);
    transpose_tf32_kernel<<<wt_grid, wt_block>>>(Wv, wvt);
    transpose_tf32_kernel<<<wt_grid, wt_block>>>(Wo, wot);

    dim3 gemm_grid(DIM / 128, MTOT / 128);   // (8, 32)
    gemm_tf32_kernel<<<gemm_grid, 256, GEMM_SMEM>>>(x, wqt, qp, nullptr);
    gemm_tf32_kernel<<<gemm_grid, 256, GEMM_SMEM>>>(x, wkt, kp, nullptr);
    gemm_tf32_kernel<<<gemm_grid, 256, GEMM_SMEM>>>(x, wvt, vp, nullptr);

    dim3 attn_grid(SEQ / 64, NH, BATCH);     // (32, 16, 2)
    attn_tc_kernel<<<attn_grid, 128, ATTN_SMEM>>>(qp, kp, vp, ap);

    gemm_tf32_kernel<<<gemm_grid, 256, GEMM_SMEM>>>(ap, wot, out, bo);
}